// round 16
// baseline (speedup 1.0000x reference)
#include <cuda_runtime.h>
#include <cuda_fp16.h>
#include <cstdint>

// ---------------- scratch ----------------
static __device__ __half g_hT16[512u * 8192u];   // 8 MB h^T in fp16 (bias added)

// XOR swizzle: 16B chunk index (bits[6:4]) ^= row%8 (bits[9:7])
#define SWZ(o) ((o) ^ (((o) >> 3) & 0x70))

__device__ __forceinline__ uint32_t smem_u32(const void* p){
    uint32_t a;
    asm("{ .reg .u64 t; cvta.to.shared.u64 t, %1; cvt.u32.u64 %0, t; }" : "=r"(a) : "l"(p));
    return a;
}
__device__ __forceinline__ void cp_async16(uint32_t dst, const void* src){
    asm volatile("cp.async.cg.shared.global [%0], [%1], 16;" :: "r"(dst), "l"(src) : "memory");
}
__device__ __forceinline__ void cp_commit(){ asm volatile("cp.async.commit_group;" ::: "memory"); }
template<int N> __device__ __forceinline__ void cp_wait(){
    asm volatile("cp.async.wait_group %0;" :: "n"(N) : "memory");
}
__device__ __forceinline__ uint32_t cvt_tf32(uint32_t bits){
    uint32_t r;
    asm("cvt.rna.tf32.f32 %0, %1;" : "=r"(r) : "f"(__uint_as_float(bits)));
    return r;
}
__device__ __forceinline__ void ldsm4(uint32_t& r0, uint32_t& r1, uint32_t& r2, uint32_t& r3,
                                      uint32_t addr){
    asm volatile("ldmatrix.sync.aligned.m8n8.x4.shared.b16 {%0,%1,%2,%3}, [%4];"
                 : "=r"(r0), "=r"(r1), "=r"(r2), "=r"(r3) : "r"(addr));
}
__device__ __forceinline__ void mma_tf32(float* c, const uint32_t* a, const uint32_t* b){
    asm volatile(
        "mma.sync.aligned.m16n8k8.row.col.f32.tf32.tf32.f32 "
        "{%0,%1,%2,%3}, {%4,%5,%6,%7}, {%8,%9}, {%0,%1,%2,%3};"
        : "+f"(c[0]), "+f"(c[1]), "+f"(c[2]), "+f"(c[3])
        : "r"(a[0]), "r"(a[1]), "r"(a[2]), "r"(a[3]), "r"(b[0]), "r"(b[1]));
}
__device__ __forceinline__ void mma_f16(float* c, const uint32_t* a, const uint32_t* b){
    asm volatile(
        "mma.sync.aligned.m16n8k16.row.col.f32.f16.f16.f32 "
        "{%0,%1,%2,%3}, {%4,%5,%6,%7}, {%8,%9}, {%0,%1,%2,%3};"
        : "+f"(c[0]), "+f"(c[1]), "+f"(c[2]), "+f"(c[3])
        : "r"(a[0]), "r"(a[1]), "r"(a[2]), "r"(a[3]), "r"(b[0]), "r"(b[1]));
}
__device__ __forceinline__ uint32_t pack_h2(float lo, float hi){
    const __half2 h = __floats2half2_rn(lo, hi);
    return *(const uint32_t*)&h;
}

// ================= GEMM1: tf32, fp16 output (validated) =================
#define G1_THREADS 256
#define G1_STAGE 49152
__global__ void __launch_bounds__(G1_THREADS, 1)
gemm1_tf32(const float* __restrict__ A, const float* __restrict__ B,
           const float* __restrict__ bias, __half* __restrict__ C,
           int ldA, int ldB, int ldC, int kiters)
{
    extern __shared__ char smem[];
    const uint32_t sb = smem_u32(smem);
    const int tid  = threadIdx.x;
    const int wid  = tid >> 5;
    const int lane = tid & 31;
    const int warp_m = wid & 1;
    const int warp_n = wid >> 1;
    const long m0 = (long)blockIdx.y * 128;
    const long n0 = (long)blockIdx.x * 256;

    float acc[4][8][4];
    #pragma unroll
    for (int i = 0; i < 4; i++)
        #pragma unroll
        for (int j = 0; j < 8; j++)
            #pragma unroll
            for (int k = 0; k < 4; k++) acc[i][j][k] = 0.0f;

    const int prow = tid >> 3;
    const int pc   = (tid & 7) * 16;

    auto copy_chunk = [&](long k0, uint32_t base, int j){
        if (j < 4){
            const int row = prow + j * 32;
            cp_async16(base + SWZ(row * 128 + pc),
                       A + (m0 + row) * (long)ldA + k0 + (pc >> 2));
        } else {
            const int row = prow + (j - 4) * 32;
            cp_async16(base + 16384u + SWZ(row * 128 + pc),
                       B + (n0 + row) * (long)ldB + k0 + (pc >> 2));
        }
    };

    const int rA  = (lane & 7) + ((lane >> 3) & 1) * 8;
    const int cbA = ((lane >> 4) & 1) * 16;
    const int rB  = (lane & 7) + ((lane >> 4) & 1) * 8;
    const int cbB = ((lane >> 3) & 1) * 16;

    auto compute = [&](int s, long k0n, uint32_t basen, bool do_copy){
        const uint32_t baseA = sb + (uint32_t)s * G1_STAGE;
        const uint32_t baseB = baseA + 16384u;
        uint32_t a[2][16], b[2][16];

        #pragma unroll
        for (int mt = 0; mt < 4; mt++){
            const int row = warp_m * 64 + mt * 16 + rA;
            ldsm4(a[0][mt*4+0], a[0][mt*4+1], a[0][mt*4+2], a[0][mt*4+3],
                  baseA + SWZ(row * 128 + cbA));
        }
        #pragma unroll
        for (int p = 0; p < 4; p++){
            const int row = warp_n * 64 + p * 16 + rB;
            ldsm4(b[0][p*4+0], b[0][p*4+1], b[0][p*4+2], b[0][p*4+3],
                  baseB + SWZ(row * 128 + cbB));
        }
        #pragma unroll
        for (int ks = 0; ks < 4; ks++){
            const int cur = ks & 1;
            const int nxt = cur ^ 1;
            const int kcn = (ks + 1) * 32;
            #pragma unroll
            for (int j = 0; j < 16; j++) b[cur][j] = cvt_tf32(b[cur][j]);
            #pragma unroll
            for (int mt = 0; mt < 4; mt++){
                if (ks < 3){
                    const int rowA = warp_m * 64 + mt * 16 + rA;
                    ldsm4(a[nxt][mt*4+0], a[nxt][mt*4+1], a[nxt][mt*4+2], a[nxt][mt*4+3],
                          baseA + SWZ(rowA * 128 + kcn + cbA));
                    const int rowB = warp_n * 64 + mt * 16 + rB;
                    ldsm4(b[nxt][mt*4+0], b[nxt][mt*4+1], b[nxt][mt*4+2], b[nxt][mt*4+3],
                          baseB + SWZ(rowB * 128 + kcn + cbB));
                }
                #pragma unroll
                for (int j = 0; j < 4; j++) a[cur][mt*4+j] = cvt_tf32(a[cur][mt*4+j]);
                #pragma unroll
                for (int nt = 0; nt < 8; nt++)
                    mma_tf32(acc[mt][nt], &a[cur][mt * 4],
                             &b[cur][(nt >> 1) * 4 + (nt & 1) * 2]);
            }
            if (do_copy){
                copy_chunk(k0n, basen, 3 * ks + 0);
                copy_chunk(k0n, basen, 3 * ks + 1);
                copy_chunk(k0n, basen, 3 * ks + 2);
            }
        }
    };

    #pragma unroll
    for (int s = 0; s < 3; s++){
        for (int j = 0; j < 12; j++)
            copy_chunk((long)s * 32, sb + (uint32_t)s * G1_STAGE, j);
        cp_commit();
    }
    for (int i = 0; i < kiters; i++){
        cp_wait<2>();
        __syncthreads();
        const bool dc = (i + 3 < kiters);
        compute(i & 3, (long)(i + 3) * 32,
                sb + (uint32_t)((i + 3) & 3) * G1_STAGE, dc);
        cp_commit();
    }

    const int gid = lane >> 2, tig = lane & 3;
    #pragma unroll
    for (int mt = 0; mt < 4; mt++){
        const long r0 = m0 + warp_m * 64 + mt * 16 + gid;
        const long r1 = r0 + 8;
        const float bv0 = __ldg(bias + r0);
        const float bv1 = __ldg(bias + r1);
        #pragma unroll
        for (int nt = 0; nt < 8; nt++){
            const long col = n0 + warp_n * 64 + nt * 8 + 2 * tig;
            const __half2 h0 = __floats2half2_rn(acc[mt][nt][0] + bv0, acc[mt][nt][1] + bv0);
            const __half2 h1 = __floats2half2_rn(acc[mt][nt][2] + bv1, acc[mt][nt][3] + bv1);
            *(__half2*)(C + r0 * ldC + col) = h0;
            *(__half2*)(C + r1 * ldC + col) = h1;
        }
    }
}

// ====== GEMM2 fused: A fp32 (cp.async, converted at fragment load), B fp16 ======
// out[m][n] = sum_k half(A[m][k]) * B16[n][k]
// Stage (64KB): A fp32 k0..31 @0 (16KB) | A fp32 k32..63 @16384 | B fp16 @32768 (32KB)
#define G2_THREADS 256
#define G2_KTILE 64
#define G2_STAGE 65536
__global__ void __launch_bounds__(G2_THREADS, 1)
gemm2_f16(const float* __restrict__ A, const __half* __restrict__ B,
          float* __restrict__ C, long ldA, int ldB, int ldC, int kiters)
{
    extern __shared__ char smem[];
    const uint32_t sb = smem_u32(smem);
    const int tid  = threadIdx.x;
    const int wid  = tid >> 5;
    const int lane = tid & 31;
    const int warp_m = wid & 1;       // 2 M-groups of 64
    const int warp_n = wid >> 1;      // 4 N-groups of 64
    const long m0 = (long)blockIdx.y * 128;
    const long n0 = (long)blockIdx.x * 256;

    float acc[4][8][4];
    #pragma unroll
    for (int i = 0; i < 4; i++)
        #pragma unroll
        for (int j = 0; j < 8; j++)
            #pragma unroll
            for (int k = 0; k < 4; k++) acc[i][j][k] = 0.0f;

    const int prow = tid >> 3;          // 0..31
    const int pc   = (tid & 7) * 16;    // 16B chunk in 128B row

    // 16 chunks/thread/stage: j 0..7 -> A fp32 (sub=j&1, rowgrp=j>>1), j 8..15 -> B
    auto copy_chunk = [&](long k0, uint32_t base, int j){
        if (j < 8){
            const int sub = j & 1;
            const int row = prow + (j >> 1) * 32;               // A: 128 rows
            cp_async16(base + (uint32_t)sub * 16384u + SWZ(row * 128 + pc),
                       A + (m0 + row) * ldA + k0 + sub * 32 + (pc >> 2));
        } else {
            const int row = prow + (j - 8) * 32;                 // B: 256 rows
            cp_async16(base + 32768u + SWZ(row * 128 + pc),
                       B + (n0 + row) * (long)ldB + k0 + (pc >> 1));
        }
    };

    // A fragment geometry (m16n8k16): reg r -> row +(r&1)*8, col +(r>>1)*8
    const int arow0 = warp_m * 64 + (lane >> 2);
    const int acol0 = (lane & 3) * 2;
    // B ldsm geometry (validated)
    const int rB  = (lane & 7) + ((lane >> 4) & 1) * 8;
    const int cbB = ((lane >> 3) & 1) * 16;

    // load + convert A fragments for (mt, ks) into dst[0..3]
    auto loadA = [&](uint32_t baseA, int mt, int ks, uint32_t* dst){
        const uint32_t sa = baseA + (uint32_t)((ks >> 1) * 16384);
        const int kin = (ks & 1) * 16;
        const int row = arow0 + mt * 16;
        const int col = kin + acol0;
        const float2 f0 = *(const float2*)(smem + (sa - sb) + SWZ(row * 128 + col * 4));
        const float2 f1 = *(const float2*)(smem + (sa - sb) + SWZ((row + 8) * 128 + col * 4));
        const float2 f2 = *(const float2*)(smem + (sa - sb) + SWZ(row * 128 + (col + 8) * 4));
        const float2 f3 = *(const float2*)(smem + (sa - sb) + SWZ((row + 8) * 128 + (col + 8) * 4));
        dst[0] = pack_h2(f0.x, f0.y);
        dst[1] = pack_h2(f1.x, f1.y);
        dst[2] = pack_h2(f2.x, f2.y);
        dst[3] = pack_h2(f3.x, f3.y);
    };

    auto compute = [&](int s, long k0n, uint32_t basen, bool do_copy){
        const uint32_t baseA = sb + (uint32_t)s * G2_STAGE;
        const uint32_t baseB = baseA + 32768u;
        uint32_t a[2][16], b[2][16];

        #pragma unroll
        for (int mt = 0; mt < 4; mt++)
            loadA(baseA, mt, 0, &a[0][mt * 4]);
        #pragma unroll
        for (int p = 0; p < 4; p++){
            const int row = warp_n * 64 + p * 16 + rB;
            ldsm4(b[0][p*4+0], b[0][p*4+1], b[0][p*4+2], b[0][p*4+3],
                  baseB + SWZ(row * 128 + cbB));
        }

        #pragma unroll
        for (int ks = 0; ks < 4; ks++){
            const int cur = ks & 1;
            const int nxt = cur ^ 1;
            const int kcn = (ks + 1) * 32;
            #pragma unroll
            for (int mt = 0; mt < 4; mt++){
                if (ks < 3){
                    loadA(baseA, mt, ks + 1, &a[nxt][mt * 4]);
                    const int rowB = warp_n * 64 + mt * 16 + rB;
                    ldsm4(b[nxt][mt*4+0], b[nxt][mt*4+1], b[nxt][mt*4+2], b[nxt][mt*4+3],
                          baseB + SWZ(rowB * 128 + kcn + cbB));
                }
                #pragma unroll
                for (int nt = 0; nt < 8; nt++)
                    mma_f16(acc[mt][nt], &a[cur][mt * 4],
                            &b[cur][(nt >> 1) * 4 + (nt & 1) * 2]);
            }
            if (do_copy){
                copy_chunk(k0n, basen, 4 * ks + 0);
                copy_chunk(k0n, basen, 4 * ks + 1);
                copy_chunk(k0n, basen, 4 * ks + 2);
                copy_chunk(k0n, basen, 4 * ks + 3);
            }
        }
    };

    // prologue: fill stages 0..1
    #pragma unroll
    for (int s = 0; s < 2; s++){
        for (int j = 0; j < 16; j++)
            copy_chunk((long)s * G2_KTILE, sb + (uint32_t)s * G2_STAGE, j);
        cp_commit();
    }
    for (int i = 0; i < kiters; i++){
        cp_wait<1>();                 // stage i resident
        __syncthreads();              // all warps done reading stage (i+2)%3
        const bool dc = (i + 2 < kiters);
        compute(i % 3, (long)(i + 2) * G2_KTILE,
                sb + (uint32_t)((i + 2) % 3) * G2_STAGE, dc);
        cp_commit();
    }

    const int gid = lane >> 2, tig = lane & 3;
    #pragma unroll
    for (int mt = 0; mt < 4; mt++){
        const long r0 = m0 + warp_m * 64 + mt * 16 + gid;
        const long r1 = r0 + 8;
        #pragma unroll
        for (int nt = 0; nt < 8; nt++){
            const long col = n0 + warp_n * 64 + nt * 8 + 2 * tig;
            *(float2*)(C + r0 * ldC + col) = make_float2(acc[mt][nt][0], acc[mt][nt][1]);
            *(float2*)(C + r1 * ldC + col) = make_float2(acc[mt][nt][2], acc[mt][nt][3]);
        }
    }
}

// ---------------- launch ----------------
extern "C" void kernel_launch(void* const* d_in, const int* in_sizes, int n_in,
                              void* d_out, int out_size)
{
    const float* input = (const float*)d_in[0];   // [8192, 512]
    const float* adj   = (const float*)d_in[1];   // [8192, 8192]
    const float* W     = (const float*)d_in[2];   // [512, 512]
    const float* bias  = (const float*)d_in[3];   // [512]
    float* out = (float*)d_out;                   // [8192, 512]

    __half* hT16 = nullptr; cudaGetSymbolAddress((void**)&hT16, g_hT16);

    const int G1_SMEM = 4 * G1_STAGE;   // 196608
    const int G2_SMEM = 3 * G2_STAGE;   // 196608
    cudaFuncSetAttribute(gemm1_tf32, cudaFuncAttributeMaxDynamicSharedMemorySize, G1_SMEM);
    cudaFuncSetAttribute(gemm2_f16,  cudaFuncAttributeMaxDynamicSharedMemorySize, G2_SMEM);

    // GEMM1 (tf32): hT16[o][n] = half(sum_i W[o][i]*input[n][i] + b[o])
    gemm1_tf32<<<dim3(8192 / 256, 512 / 128), G1_THREADS, G1_SMEM>>>(
        W, input, bias, hT16, 512, 512, 8192, 512 / 32);

    // GEMM2 (fused fp32->fp16 A): out[m][o] = sum_k half(adj[m][k]) * hT16[o][k]
    gemm2_f16<<<dim3(512 / 256, 8192 / 128), G2_THREADS, G2_SMEM>>>(
        adj, hT16, out, 8192L, 8192, 512, 8192 / G2_KTILE);
}

// round 17
// speedup vs baseline: 1.2081x; 1.2081x over previous
#include <cuda_runtime.h>
#include <cuda_fp16.h>
#include <cstdint>

// ---------------- scratch ----------------
static __device__ __half g_adj16[8192ull * 8192ull];   // 128 MB adj in fp16
static __device__ __half g_hT16[512u * 8192u];         // 8 MB  h^T in fp16 (bias added)

// XOR swizzle: 16B chunk index (bits[6:4]) ^= row%8 (bits[9:7])
#define SWZ(o) ((o) ^ (((o) >> 3) & 0x70))

__device__ __forceinline__ uint32_t smem_u32(const void* p){
    uint32_t a;
    asm("{ .reg .u64 t; cvta.to.shared.u64 t, %1; cvt.u32.u64 %0, t; }" : "=r"(a) : "l"(p));
    return a;
}
__device__ __forceinline__ void cp_async16(uint32_t dst, const void* src){
    asm volatile("cp.async.cg.shared.global [%0], [%1], 16;" :: "r"(dst), "l"(src) : "memory");
}
__device__ __forceinline__ void cp_commit(){ asm volatile("cp.async.commit_group;" ::: "memory"); }
template<int N> __device__ __forceinline__ void cp_wait(){
    asm volatile("cp.async.wait_group %0;" :: "n"(N) : "memory");
}
__device__ __forceinline__ uint32_t cvt_tf32(uint32_t bits){
    uint32_t r;
    asm("cvt.rna.tf32.f32 %0, %1;" : "=r"(r) : "f"(__uint_as_float(bits)));
    return r;
}
__device__ __forceinline__ void ldsm4(uint32_t& r0, uint32_t& r1, uint32_t& r2, uint32_t& r3,
                                      uint32_t addr){
    asm volatile("ldmatrix.sync.aligned.m8n8.x4.shared.b16 {%0,%1,%2,%3}, [%4];"
                 : "=r"(r0), "=r"(r1), "=r"(r2), "=r"(r3) : "r"(addr));
}
__device__ __forceinline__ void mma_tf32(float* c, const uint32_t* a, const uint32_t* b){
    asm volatile(
        "mma.sync.aligned.m16n8k8.row.col.f32.tf32.tf32.f32 "
        "{%0,%1,%2,%3}, {%4,%5,%6,%7}, {%8,%9}, {%0,%1,%2,%3};"
        : "+f"(c[0]), "+f"(c[1]), "+f"(c[2]), "+f"(c[3])
        : "r"(a[0]), "r"(a[1]), "r"(a[2]), "r"(a[3]), "r"(b[0]), "r"(b[1]));
}
__device__ __forceinline__ void mma_f16(float* c, const uint32_t* a, const uint32_t* b){
    asm volatile(
        "mma.sync.aligned.m16n8k16.row.col.f32.f16.f16.f32 "
        "{%0,%1,%2,%3}, {%4,%5,%6,%7}, {%8,%9}, {%0,%1,%2,%3};"
        : "+f"(c[0]), "+f"(c[1]), "+f"(c[2]), "+f"(c[3])
        : "r"(a[0]), "r"(a[1]), "r"(a[2]), "r"(a[3]), "r"(b[0]), "r"(b[1]));
}

// ====== convert: adj fp32 -> fp16 (rn); 32B loads, 16B stores, streaming ======
// Each logical element = 8 floats (two float4) -> one uint4 of 8 fp16.
__global__ void __launch_bounds__(256)
cvt_f32_to_f16(const float4* __restrict__ src, uint4* __restrict__ dst, int n8)
{
    const int stride = gridDim.x * blockDim.x;
    int i = blockIdx.x * blockDim.x + threadIdx.x;
    // n8 = 8388608 = 16 * (2048*256): exact 4x-unrolled loop, no tail
    for (; i + 3 * stride < n8; i += 4 * stride){
        const int i0 = i, i1 = i + stride, i2 = i + 2 * stride, i3 = i + 3 * stride;
        const float4 u0 = __ldcs(src + 2 * (long)i0);
        const float4 v0 = __ldcs(src + 2 * (long)i0 + 1);
        const float4 u1 = __ldcs(src + 2 * (long)i1);
        const float4 v1 = __ldcs(src + 2 * (long)i1 + 1);
        const float4 u2 = __ldcs(src + 2 * (long)i2);
        const float4 v2 = __ldcs(src + 2 * (long)i2 + 1);
        const float4 u3 = __ldcs(src + 2 * (long)i3);
        const float4 v3 = __ldcs(src + 2 * (long)i3 + 1);
        uint4 o0, o1, o2, o3;
        {
            __half2 a = __floats2half2_rn(u0.x, u0.y), b = __floats2half2_rn(u0.z, u0.w);
            __half2 c = __floats2half2_rn(v0.x, v0.y), d = __floats2half2_rn(v0.z, v0.w);
            o0 = make_uint4(*(uint32_t*)&a, *(uint32_t*)&b, *(uint32_t*)&c, *(uint32_t*)&d);
        }
        {
            __half2 a = __floats2half2_rn(u1.x, u1.y), b = __floats2half2_rn(u1.z, u1.w);
            __half2 c = __floats2half2_rn(v1.x, v1.y), d = __floats2half2_rn(v1.z, v1.w);
            o1 = make_uint4(*(uint32_t*)&a, *(uint32_t*)&b, *(uint32_t*)&c, *(uint32_t*)&d);
        }
        {
            __half2 a = __floats2half2_rn(u2.x, u2.y), b = __floats2half2_rn(u2.z, u2.w);
            __half2 c = __floats2half2_rn(v2.x, v2.y), d = __floats2half2_rn(v2.z, v2.w);
            o2 = make_uint4(*(uint32_t*)&a, *(uint32_t*)&b, *(uint32_t*)&c, *(uint32_t*)&d);
        }
        {
            __half2 a = __floats2half2_rn(u3.x, u3.y), b = __floats2half2_rn(u3.z, u3.w);
            __half2 c = __floats2half2_rn(v3.x, v3.y), d = __floats2half2_rn(v3.z, v3.w);
            o3 = make_uint4(*(uint32_t*)&a, *(uint32_t*)&b, *(uint32_t*)&c, *(uint32_t*)&d);
        }
        __stcs(dst + i0, o0);
        __stcs(dst + i1, o1);
        __stcs(dst + i2, o2);
        __stcs(dst + i3, o3);
    }
    for (; i < n8; i += stride){
        const float4 u = __ldcs(src + 2 * (long)i);
        const float4 v = __ldcs(src + 2 * (long)i + 1);
        __half2 a = __floats2half2_rn(u.x, u.y), b = __floats2half2_rn(u.z, u.w);
        __half2 c = __floats2half2_rn(v.x, v.y), d = __floats2half2_rn(v.z, v.w);
        __stcs(dst + i, make_uint4(*(uint32_t*)&a, *(uint32_t*)&b,
                                   *(uint32_t*)&c, *(uint32_t*)&d));
    }
}

// ================= GEMM1: tf32, fp16 output (validated) =================
#define G1_THREADS 256
#define G1_STAGE 49152
__global__ void __launch_bounds__(G1_THREADS, 1)
gemm1_tf32(const float* __restrict__ A, const float* __restrict__ B,
           const float* __restrict__ bias, __half* __restrict__ C,
           int ldA, int ldB, int ldC, int kiters)
{
    extern __shared__ char smem[];
    const uint32_t sb = smem_u32(smem);
    const int tid  = threadIdx.x;
    const int wid  = tid >> 5;
    const int lane = tid & 31;
    const int warp_m = wid & 1;
    const int warp_n = wid >> 1;
    const long m0 = (long)blockIdx.y * 128;
    const long n0 = (long)blockIdx.x * 256;

    float acc[4][8][4];
    #pragma unroll
    for (int i = 0; i < 4; i++)
        #pragma unroll
        for (int j = 0; j < 8; j++)
            #pragma unroll
            for (int k = 0; k < 4; k++) acc[i][j][k] = 0.0f;

    const int prow = tid >> 3;
    const int pc   = (tid & 7) * 16;

    auto copy_chunk = [&](long k0, uint32_t base, int j){
        if (j < 4){
            const int row = prow + j * 32;
            cp_async16(base + SWZ(row * 128 + pc),
                       A + (m0 + row) * (long)ldA + k0 + (pc >> 2));
        } else {
            const int row = prow + (j - 4) * 32;
            cp_async16(base + 16384u + SWZ(row * 128 + pc),
                       B + (n0 + row) * (long)ldB + k0 + (pc >> 2));
        }
    };

    const int rA  = (lane & 7) + ((lane >> 3) & 1) * 8;
    const int cbA = ((lane >> 4) & 1) * 16;
    const int rB  = (lane & 7) + ((lane >> 4) & 1) * 8;
    const int cbB = ((lane >> 3) & 1) * 16;

    auto compute = [&](int s, long k0n, uint32_t basen, bool do_copy){
        const uint32_t baseA = sb + (uint32_t)s * G1_STAGE;
        const uint32_t baseB = baseA + 16384u;
        uint32_t a[2][16], b[2][16];

        #pragma unroll
        for (int mt = 0; mt < 4; mt++){
            const int row = warp_m * 64 + mt * 16 + rA;
            ldsm4(a[0][mt*4+0], a[0][mt*4+1], a[0][mt*4+2], a[0][mt*4+3],
                  baseA + SWZ(row * 128 + cbA));
        }
        #pragma unroll
        for (int p = 0; p < 4; p++){
            const int row = warp_n * 64 + p * 16 + rB;
            ldsm4(b[0][p*4+0], b[0][p*4+1], b[0][p*4+2], b[0][p*4+3],
                  baseB + SWZ(row * 128 + cbB));
        }
        #pragma unroll
        for (int ks = 0; ks < 4; ks++){
            const int cur = ks & 1;
            const int nxt = cur ^ 1;
            const int kcn = (ks + 1) * 32;
            #pragma unroll
            for (int j = 0; j < 16; j++) b[cur][j] = cvt_tf32(b[cur][j]);
            #pragma unroll
            for (int mt = 0; mt < 4; mt++){
                if (ks < 3){
                    const int rowA = warp_m * 64 + mt * 16 + rA;
                    ldsm4(a[nxt][mt*4+0], a[nxt][mt*4+1], a[nxt][mt*4+2], a[nxt][mt*4+3],
                          baseA + SWZ(rowA * 128 + kcn + cbA));
                    const int rowB = warp_n * 64 + mt * 16 + rB;
                    ldsm4(b[nxt][mt*4+0], b[nxt][mt*4+1], b[nxt][mt*4+2], b[nxt][mt*4+3],
                          baseB + SWZ(rowB * 128 + kcn + cbB));
                }
                #pragma unroll
                for (int j = 0; j < 4; j++) a[cur][mt*4+j] = cvt_tf32(a[cur][mt*4+j]);
                #pragma unroll
                for (int nt = 0; nt < 8; nt++)
                    mma_tf32(acc[mt][nt], &a[cur][mt * 4],
                             &b[cur][(nt >> 1) * 4 + (nt & 1) * 2]);
            }
            if (do_copy){
                copy_chunk(k0n, basen, 3 * ks + 0);
                copy_chunk(k0n, basen, 3 * ks + 1);
                copy_chunk(k0n, basen, 3 * ks + 2);
            }
        }
    };

    #pragma unroll
    for (int s = 0; s < 3; s++){
        for (int j = 0; j < 12; j++)
            copy_chunk((long)s * 32, sb + (uint32_t)s * G1_STAGE, j);
        cp_commit();
    }
    for (int i = 0; i < kiters; i++){
        cp_wait<2>();
        __syncthreads();
        const bool dc = (i + 3 < kiters);
        compute(i & 3, (long)(i + 3) * 32,
                sb + (uint32_t)((i + 3) & 3) * G1_STAGE, dc);
        cp_commit();
    }

    const int gid = lane >> 2, tig = lane & 3;
    #pragma unroll
    for (int mt = 0; mt < 4; mt++){
        const long r0 = m0 + warp_m * 64 + mt * 16 + gid;
        const long r1 = r0 + 8;
        const float bv0 = __ldg(bias + r0);
        const float bv1 = __ldg(bias + r1);
        #pragma unroll
        for (int nt = 0; nt < 8; nt++){
            const long col = n0 + warp_n * 64 + nt * 8 + 2 * tig;
            const __half2 h0 = __floats2half2_rn(acc[mt][nt][0] + bv0, acc[mt][nt][1] + bv0);
            const __half2 h1 = __floats2half2_rn(acc[mt][nt][2] + bv1, acc[mt][nt][3] + bv1);
            *(__half2*)(C + r0 * ldC + col) = h0;
            *(__half2*)(C + r1 * ldC + col) = h1;
        }
    }
}

// ================= GEMM2: fp16 inputs, fp32 out (validated R9) =================
#define G2_THREADS 256
#define G2_KTILE 64          // fp16 elements: 128B rows
#define G2_STAGE 49152       // A 16KB + B 32KB
__global__ void __launch_bounds__(G2_THREADS, 1)
gemm2_f16(const __half* __restrict__ A, const __half* __restrict__ B,
          float* __restrict__ C, int ldA, int ldB, int ldC, int kiters)
{
    extern __shared__ char smem[];
    const uint32_t sb = smem_u32(smem);
    const int tid  = threadIdx.x;
    const int wid  = tid >> 5;
    const int lane = tid & 31;
    const int warp_m = wid & 1;       // 2 M-groups of 64
    const int warp_n = wid >> 1;      // 4 N-groups of 64
    const long m0 = (long)blockIdx.y * 128;
    const long n0 = (long)blockIdx.x * 256;

    float acc[4][8][4];
    #pragma unroll
    for (int i = 0; i < 4; i++)
        #pragma unroll
        for (int j = 0; j < 8; j++)
            #pragma unroll
            for (int k = 0; k < 4; k++) acc[i][j][k] = 0.0f;

    const int prow = tid >> 3;          // 0..31
    const int pc   = (tid & 7) * 16;    // byte chunk in 128B row

    auto copy_chunk = [&](long k0, uint32_t base, int j){
        if (j < 4){
            const int row = prow + j * 32;                       // A: 128 rows
            cp_async16(base + SWZ(row * 128 + pc),
                       A + (m0 + row) * (long)ldA + k0 + (pc >> 1));
        } else {
            const int row = prow + (j - 4) * 32;                 // B: 256 rows
            cp_async16(base + 16384u + SWZ(row * 128 + pc),
                       B + (n0 + row) * (long)ldB + k0 + (pc >> 1));
        }
    };

    const int rA  = (lane & 7) + ((lane >> 3) & 1) * 8;
    const int cbA = ((lane >> 4) & 1) * 16;
    const int rB  = (lane & 7) + ((lane >> 4) & 1) * 8;
    const int cbB = ((lane >> 3) & 1) * 16;

    auto compute = [&](int s, long k0n, uint32_t basen, bool do_copy){
        const uint32_t baseA = sb + (uint32_t)s * G2_STAGE;
        const uint32_t baseB = baseA + 16384u;
        uint32_t a[2][16], b[2][16];

        #pragma unroll
        for (int mt = 0; mt < 4; mt++){
            const int row = warp_m * 64 + mt * 16 + rA;
            ldsm4(a[0][mt*4+0], a[0][mt*4+1], a[0][mt*4+2], a[0][mt*4+3],
                  baseA + SWZ(row * 128 + cbA));
        }
        #pragma unroll
        for (int p = 0; p < 4; p++){
            const int row = warp_n * 64 + p * 16 + rB;
            ldsm4(b[0][p*4+0], b[0][p*4+1], b[0][p*4+2], b[0][p*4+3],
                  baseB + SWZ(row * 128 + cbB));
        }

        #pragma unroll
        for (int ks = 0; ks < 4; ks++){
            const int cur = ks & 1;
            const int nxt = cur ^ 1;
            const int kcn = (ks + 1) * 32;
            #pragma unroll
            for (int mt = 0; mt < 4; mt++){
                if (ks < 3){
                    const int rowA = warp_m * 64 + mt * 16 + rA;
                    ldsm4(a[nxt][mt*4+0], a[nxt][mt*4+1], a[nxt][mt*4+2], a[nxt][mt*4+3],
                          baseA + SWZ(rowA * 128 + kcn + cbA));
                    const int rowB = warp_n * 64 + mt * 16 + rB;
                    ldsm4(b[nxt][mt*4+0], b[nxt][mt*4+1], b[nxt][mt*4+2], b[nxt][mt*4+3],
                          baseB + SWZ(rowB * 128 + kcn + cbB));
                }
                #pragma unroll
                for (int nt = 0; nt < 8; nt++)
                    mma_f16(acc[mt][nt], &a[cur][mt * 4],
                            &b[cur][(nt >> 1) * 4 + (nt & 1) * 2]);
            }
            if (do_copy){
                copy_chunk(k0n, basen, 3 * ks + 0);
                copy_chunk(k0n, basen, 3 * ks + 1);
                copy_chunk(k0n, basen, 3 * ks + 2);
            }
        }
    };

    #pragma unroll
    for (int s = 0; s < 3; s++){
        for (int j = 0; j < 12; j++)
            copy_chunk((long)s * G2_KTILE, sb + (uint32_t)s * G2_STAGE, j);
        cp_commit();
    }
    for (int i = 0; i < kiters; i++){
        cp_wait<2>();
        __syncthreads();
        const bool dc = (i + 3 < kiters);
        compute(i & 3, (long)(i + 3) * G2_KTILE,
                sb + (uint32_t)((i + 3) & 3) * G2_STAGE, dc);
        cp_commit();
    }

    const int gid = lane >> 2, tig = lane & 3;
    #pragma unroll
    for (int mt = 0; mt < 4; mt++){
        const long r0 = m0 + warp_m * 64 + mt * 16 + gid;
        const long r1 = r0 + 8;
        #pragma unroll
        for (int nt = 0; nt < 8; nt++){
            const long col = n0 + warp_n * 64 + nt * 8 + 2 * tig;
            *(float2*)(C + r0 * ldC + col) = make_float2(acc[mt][nt][0], acc[mt][nt][1]);
            *(float2*)(C + r1 * ldC + col) = make_float2(acc[mt][nt][2], acc[mt][nt][3]);
        }
    }
}

// ---------------- launch (validated R9 fork/join) ----------------
extern "C" void kernel_launch(void* const* d_in, const int* in_sizes, int n_in,
                              void* d_out, int out_size)
{
    const float* input = (const float*)d_in[0];   // [8192, 512]
    const float* adj   = (const float*)d_in[1];   // [8192, 8192]
    const float* W     = (const float*)d_in[2];   // [512, 512]
    const float* bias  = (const float*)d_in[3];   // [512]
    float* out = (float*)d_out;                   // [8192, 512]

    __half* adj16 = nullptr; cudaGetSymbolAddress((void**)&adj16, g_adj16);
    __half* hT16  = nullptr; cudaGetSymbolAddress((void**)&hT16,  g_hT16);

    const int G1_SMEM = 4 * G1_STAGE;   // 196608
    const int G2_SMEM = 4 * G2_STAGE;   // 196608
    cudaFuncSetAttribute(gemm1_tf32, cudaFuncAttributeMaxDynamicSharedMemorySize, G1_SMEM);
    cudaFuncSetAttribute(gemm2_f16,  cudaFuncAttributeMaxDynamicSharedMemorySize, G2_SMEM);

    cudaStream_t s2;
    cudaStreamCreateWithFlags(&s2, cudaStreamNonBlocking);
    cudaEvent_t eFork, eJoin;
    cudaEventCreateWithFlags(&eFork, cudaEventDisableTiming);
    cudaEventCreateWithFlags(&eJoin, cudaEventDisableTiming);

    cudaEventRecord(eFork, 0);
    cudaStreamWaitEvent(s2, eFork, 0);

    // side stream: GEMM1 (tensor-bound) overlaps the DRAM-bound cvt
    gemm1_tf32<<<dim3(8192 / 256, 512 / 128), G1_THREADS, G1_SMEM, s2>>>(
        W, input, bias, hT16, 512, 512, 8192, 512 / 32);
    cudaEventRecord(eJoin, s2);

    // main stream: adj -> fp16 (rn), streaming, 16B stores
    cvt_f32_to_f16<<<2048, 256>>>((const float4*)adj, (uint4*)adj16, 8192 * 8192 / 8);

    // join, then GEMM2
    cudaStreamWaitEvent(0, eJoin, 0);
    gemm2_f16<<<dim3(512 / 256, 8192 / 128), G2_THREADS, G2_SMEM>>>(
        adj16, hT16, out, 8192, 8192, 512, 8192 / G2_KTILE);

    cudaEventDestroy(eFork);
    cudaEventDestroy(eJoin);
    cudaStreamDestroy(s2);
}